// round 7
// baseline (speedup 1.0000x reference)
#include <cuda_runtime.h>
#include <cstdint>

// Problem: out[N=100000,128] = zeros; out[i1]+=deltas[:,:128]; out[i2]+=deltas[:,128:256];
//          b = deltas[:,256:320].  d_out layout: [ out : N*128 fp32 ][ b : E*64 fp32 ]
//
// R6 = R3 (best: 151.9us, occ 94.6%) with two fixes:
//  - single persistent wave: 1184 blocks (148 SMs x 8 resident blocks) instead of
//    2048 (1.73 waves, ragged tail)
//  - hoist ONLY the index loads (2 int regs) above the TMA-drain wait; R5 showed
//    hoisting the float payloads costs 4 regs -> 6 blocks/SM -> occ 68%.

#define WARPS_PER_BLOCK 8
#define THREADS_PER_BLOCK (WARPS_PER_BLOCK * 32)
#define GRID_BLOCKS 1184  // 148 SMs * 8 resident blocks -> exactly one wave

__device__ __forceinline__ uint64_t make_evict_last_policy() {
    uint64_t pol;
    asm("createpolicy.fractional.L2::evict_last.b64 %0, 1.0;" : "=l"(pol));
    return pol;
}

__device__ __forceinline__ uint64_t make_evict_first_policy() {
    uint64_t pol;
    asm("createpolicy.fractional.L2::evict_first.b64 %0, 1.0;" : "=l"(pol));
    return pol;
}

__global__ void zero_out_kernel(float4* __restrict__ out4, long n4) {
    long i = blockIdx.x * (long)blockDim.x + threadIdx.x;
    if (i < n4) {
        uint64_t pol = make_evict_last_policy();
        asm volatile("st.global.L2::cache_hint.v4.f32 [%0], {%1,%2,%3,%4}, %5;"
                     :: "l"(out4 + i), "f"(0.f), "f"(0.f), "f"(0.f), "f"(0.f), "l"(pol)
                     : "memory");
    }
}

__device__ __forceinline__ float4 ldg_stream(const float4* p, uint64_t pol) {
    float4 v;
    asm("ld.global.nc.L2::cache_hint.v4.f32 {%0,%1,%2,%3}, [%4], %5;"
        : "=f"(v.x), "=f"(v.y), "=f"(v.z), "=f"(v.w) : "l"(p), "l"(pol));
    return v;
}

__device__ __forceinline__ void stg_stream(float4* p, float4 v) {
    asm volatile("st.global.cs.v4.f32 [%0], {%1,%2,%3,%4};"
                 :: "l"(p), "f"(v.x), "f"(v.y), "f"(v.z), "f"(v.w)
                 : "memory");
}

__device__ __forceinline__ void bulk_reduce_add_f32(float* gdst, uint32_t ssrc,
                                                    uint32_t bytes, uint64_t pol) {
    asm volatile(
        "cp.reduce.async.bulk.global.shared::cta.bulk_group.L2::cache_hint.add.f32 "
        "[%0], [%1], %2, %3;"
        :: "l"(gdst), "r"(ssrc), "r"(bytes), "l"(pol)
        : "memory");
}

__global__ void __launch_bounds__(THREADS_PER_BLOCK, 8)
scatter_kernel(const float4* __restrict__ deltas4,  // E * 80 float4
               const int*    __restrict__ i1,       // E
               const int*    __restrict__ i2,       // E
               float*        __restrict__ out,      // N * 128 fp32
               float4*       __restrict__ bout4,    // E * 16 float4
               long E, long nwarps)
{
    // Per-warp double buffer: 2 x 64 float4 = 2 KB/warp, 16 KB/block.
    __shared__ __align__(16) float4 buf[WARPS_PER_BLOCK][2][64];

    const int wid  = threadIdx.x >> 5;
    const int lane = threadIdx.x & 31;
    const long gw  = (long)blockIdx.x * WARPS_PER_BLOCK + wid;

    const uint64_t pol_ef = make_evict_first_policy();
    const uint64_t pol_el = make_evict_last_policy();

    int parity = 0;
    for (long e = gw; e < E; e += nwarps, parity ^= 1) {
        // Cheap hoist: index loads only (2 int regs).
        int r1 = __ldg(&i1[e]);
        int r2 = __ldg(&i2[e]);

        // Reclaim this parity's buffer (handed to TMA 2 iterations ago).
        if (lane == 0)
            asm volatile("cp.async.bulk.wait_group.read 1;" ::: "memory");
        __syncwarp();

        const float4* row = deltas4 + e * 80;

        // ux: chunks [0,32) ; uy: chunks [32,64) -> SMEM (coalesced)
        float4 v0 = ldg_stream(row + lane,      pol_ef);
        float4 v1 = ldg_stream(row + 32 + lane, pol_ef);
        buf[wid][parity][lane]      = v0;
        buf[wid][parity][32 + lane] = v1;

        // b: chunks [64,80) -> straight to output, bypass SMEM
        if (lane < 16) {
            float4 vb = ldg_stream(row + 64 + lane, pol_ef);
            stg_stream(bout4 + e * 16 + lane, vb);
        }
        __syncwarp();

        if (lane == 0) {
            asm volatile("fence.proxy.async.shared::cta;" ::: "memory");
            uint32_t s = (uint32_t)__cvta_generic_to_shared(&buf[wid][parity][0]);
            bulk_reduce_add_f32(out + (long)r1 * 128, s,       512, pol_el);
            bulk_reduce_add_f32(out + (long)r2 * 128, s + 512, 512, pol_el);
            asm volatile("cp.async.bulk.commit_group;" ::: "memory");
        }
    }

    // Drain all pending bulk groups before exit.
    if (lane == 0)
        asm volatile("cp.async.bulk.wait_group 0;" ::: "memory");
}

extern "C" void kernel_launch(void* const* d_in, const int* in_sizes, int n_in,
                              void* d_out, int out_size)
{
    // metadata order: unary(N*128 f32), binary(E*64 f32), deltas(E*320 f32),
    //                 index1(E i32), index2(E i32)
    const long N = in_sizes[0] / 128;
    const long E = in_sizes[2] / 320;

    const float4* deltas4 = (const float4*)d_in[2];
    const int*    i1      = (const int*)d_in[3];
    const int*    i2      = (const int*)d_in[4];

    float*  out   = (float*)d_out;                       // N*128
    float4* bout4 = (float4*)((float*)d_out + N * 128);  // E*16 float4

    // 1) zero the scatter target and pin it in L2 (evict_last)
    {
        long n4 = (N * 128) / 4;
        int  threads = 256;
        long blocks = (n4 + threads - 1) / threads;
        zero_out_kernel<<<(unsigned)blocks, threads>>>((float4*)out, n4);
    }

    // 2) scatter-add (TMA bulk-reduce) + b copy — single persistent wave
    {
        long nwarps = (long)GRID_BLOCKS * WARPS_PER_BLOCK;  // 9472 warps
        scatter_kernel<<<GRID_BLOCKS, THREADS_PER_BLOCK>>>(deltas4, i1, i2, out, bout4, E, nwarps);
    }
}

// round 8
// speedup vs baseline: 1.0535x; 1.0535x over previous
#include <cuda_runtime.h>
#include <cstdint>

// Problem: out[N=100000,128] = zeros; out[i1]+=deltas[:,:128]; out[i2]+=deltas[:,128:256];
//          b = deltas[:,256:320].  d_out layout: [ out : N*128 fp32 ][ b : E*64 fp32 ]
//
// R7 = R3 (best scatter: 145.7us @ grid 2048) + two tweaks:
//  - grid 4096: shorter per-warp TMA dependency chains (R6 showed persistent
//    1184-block grid is WORSE; more, shorter-lived blocks are better)
//  - TMA issue split across lane0 (ux reduce) and lane1 (uy reduce): bulk-group
//    state is per-thread, so each lane's commit/wait chain halves.

#define WARPS_PER_BLOCK 8
#define THREADS_PER_BLOCK (WARPS_PER_BLOCK * 32)
#define GRID_BLOCKS 4096

__device__ __forceinline__ uint64_t make_evict_last_policy() {
    uint64_t pol;
    asm("createpolicy.fractional.L2::evict_last.b64 %0, 1.0;" : "=l"(pol));
    return pol;
}

__device__ __forceinline__ uint64_t make_evict_first_policy() {
    uint64_t pol;
    asm("createpolicy.fractional.L2::evict_first.b64 %0, 1.0;" : "=l"(pol));
    return pol;
}

__global__ void zero_out_kernel(float4* __restrict__ out4, long n4) {
    long i = blockIdx.x * (long)blockDim.x + threadIdx.x;
    if (i < n4) {
        uint64_t pol = make_evict_last_policy();
        asm volatile("st.global.L2::cache_hint.v4.f32 [%0], {%1,%2,%3,%4}, %5;"
                     :: "l"(out4 + i), "f"(0.f), "f"(0.f), "f"(0.f), "f"(0.f), "l"(pol)
                     : "memory");
    }
}

__device__ __forceinline__ float4 ldg_stream(const float4* p, uint64_t pol) {
    float4 v;
    asm("ld.global.nc.L2::cache_hint.v4.f32 {%0,%1,%2,%3}, [%4], %5;"
        : "=f"(v.x), "=f"(v.y), "=f"(v.z), "=f"(v.w) : "l"(p), "l"(pol));
    return v;
}

__device__ __forceinline__ void stg_stream(float4* p, float4 v) {
    asm volatile("st.global.cs.v4.f32 [%0], {%1,%2,%3,%4};"
                 :: "l"(p), "f"(v.x), "f"(v.y), "f"(v.z), "f"(v.w)
                 : "memory");
}

__device__ __forceinline__ void bulk_reduce_add_f32(float* gdst, uint32_t ssrc,
                                                    uint32_t bytes, uint64_t pol) {
    asm volatile(
        "cp.reduce.async.bulk.global.shared::cta.bulk_group.L2::cache_hint.add.f32 "
        "[%0], [%1], %2, %3;"
        :: "l"(gdst), "r"(ssrc), "r"(bytes), "l"(pol)
        : "memory");
}

__global__ void __launch_bounds__(THREADS_PER_BLOCK, 8)
scatter_kernel(const float4* __restrict__ deltas4,  // E * 80 float4
               const int*    __restrict__ i1,       // E
               const int*    __restrict__ i2,       // E
               float*        __restrict__ out,      // N * 128 fp32
               float4*       __restrict__ bout4,    // E * 16 float4
               long E, long nwarps)
{
    // Per-warp double buffer: 2 x 64 float4 = 2 KB/warp, 16 KB/block.
    __shared__ __align__(16) float4 buf[WARPS_PER_BLOCK][2][64];

    const int wid  = threadIdx.x >> 5;
    const int lane = threadIdx.x & 31;
    const long gw  = (long)blockIdx.x * WARPS_PER_BLOCK + wid;

    const uint64_t pol_ef = make_evict_first_policy();
    const uint64_t pol_el = make_evict_last_policy();

    int parity = 0;
    for (long e = gw; e < E; e += nwarps, parity ^= 1) {
        // Reclaim this parity's buffer half (each issuing lane tracks its own
        // bulk-group chain; lane0 owns bytes [0,512), lane1 owns [512,1024)).
        if (lane < 2)
            asm volatile("cp.async.bulk.wait_group.read 1;" ::: "memory");
        __syncwarp();

        const float4* row = deltas4 + e * 80;

        // ux: chunks [0,32) ; uy: chunks [32,64) -> SMEM (coalesced)
        float4 v0 = ldg_stream(row + lane,      pol_ef);
        float4 v1 = ldg_stream(row + 32 + lane, pol_ef);
        buf[wid][parity][lane]      = v0;
        buf[wid][parity][32 + lane] = v1;

        // b: chunks [64,80) -> straight to output, bypass SMEM
        if (lane < 16) {
            float4 vb = ldg_stream(row + 64 + lane, pol_ef);
            stg_stream(bout4 + e * 16 + lane, vb);
        }
        __syncwarp();

        if (lane < 2) {
            asm volatile("fence.proxy.async.shared::cta;" ::: "memory");
            uint32_t s = (uint32_t)__cvta_generic_to_shared(&buf[wid][parity][0]);
            if (lane == 0) {
                int r1 = __ldg(&i1[e]);
                bulk_reduce_add_f32(out + (long)r1 * 128, s, 512, pol_el);
            } else {
                int r2 = __ldg(&i2[e]);
                bulk_reduce_add_f32(out + (long)r2 * 128, s + 512, 512, pol_el);
            }
            asm volatile("cp.async.bulk.commit_group;" ::: "memory");
        }
    }

    // Drain all pending bulk groups before exit.
    if (lane < 2)
        asm volatile("cp.async.bulk.wait_group 0;" ::: "memory");
}

extern "C" void kernel_launch(void* const* d_in, const int* in_sizes, int n_in,
                              void* d_out, int out_size)
{
    // metadata order: unary(N*128 f32), binary(E*64 f32), deltas(E*320 f32),
    //                 index1(E i32), index2(E i32)
    const long N = in_sizes[0] / 128;
    const long E = in_sizes[2] / 320;

    const float4* deltas4 = (const float4*)d_in[2];
    const int*    i1      = (const int*)d_in[3];
    const int*    i2      = (const int*)d_in[4];

    float*  out   = (float*)d_out;                       // N*128
    float4* bout4 = (float4*)((float*)d_out + N * 128);  // E*16 float4

    // 1) zero the scatter target and pin it in L2 (evict_last)
    {
        long n4 = (N * 128) / 4;
        int  threads = 256;
        long blocks = (n4 + threads - 1) / threads;
        zero_out_kernel<<<(unsigned)blocks, threads>>>((float4*)out, n4);
    }

    // 2) scatter-add (TMA bulk-reduce) + b copy
    {
        long nwarps = (long)GRID_BLOCKS * WARPS_PER_BLOCK;
        scatter_kernel<<<GRID_BLOCKS, THREADS_PER_BLOCK>>>(deltas4, i1, i2, out, bout4, E, nwarps);
    }
}

// round 9
// speedup vs baseline: 1.0837x; 1.0287x over previous
#include <cuda_runtime.h>
#include <cstdint>

// Problem: out[N=100000,128] = zeros; out[i1]+=deltas[:,:128]; out[i2]+=deltas[:,128:256];
//          b = deltas[:,256:320].  d_out layout: [ out : N*128 fp32 ][ b : E*64 fp32 ]
//
// R8 = R3 structure (grid 2048, lane0 TMA, 8 warps/block) but the ux/uy loads go
// through cp.async (LDGSTS, zero register cost) into a 3-stage SMEM ring,
// prefetched ONE EDGE AHEAD so the ~600cyc DRAM load latency overlaps the loop
// body instead of sitting on the critical path. 3 stages are required so the
// stage being prefetch-written was TMA-read 2 bulk-groups ago (wait_group.read 1).

#define WARPS_PER_BLOCK 8
#define THREADS_PER_BLOCK (WARPS_PER_BLOCK * 32)
#define GRID_BLOCKS 2048
#define STAGES 3
#define STAGE_BYTES 1024  // 64 float4 = ux(512) || uy(512)

__device__ __forceinline__ uint64_t make_evict_last_policy() {
    uint64_t pol;
    asm("createpolicy.fractional.L2::evict_last.b64 %0, 1.0;" : "=l"(pol));
    return pol;
}

__device__ __forceinline__ uint64_t make_evict_first_policy() {
    uint64_t pol;
    asm("createpolicy.fractional.L2::evict_first.b64 %0, 1.0;" : "=l"(pol));
    return pol;
}

__global__ void zero_out_kernel(float4* __restrict__ out4, long n4) {
    long i = blockIdx.x * (long)blockDim.x + threadIdx.x;
    if (i < n4) {
        uint64_t pol = make_evict_last_policy();
        asm volatile("st.global.L2::cache_hint.v4.f32 [%0], {%1,%2,%3,%4}, %5;"
                     :: "l"(out4 + i), "f"(0.f), "f"(0.f), "f"(0.f), "f"(0.f), "l"(pol)
                     : "memory");
    }
}

__device__ __forceinline__ float4 ldg_stream(const float4* p, uint64_t pol) {
    float4 v;
    asm("ld.global.nc.L2::cache_hint.v4.f32 {%0,%1,%2,%3}, [%4], %5;"
        : "=f"(v.x), "=f"(v.y), "=f"(v.z), "=f"(v.w) : "l"(p), "l"(pol));
    return v;
}

__device__ __forceinline__ void stg_stream(float4* p, float4 v) {
    asm volatile("st.global.cs.v4.f32 [%0], {%1,%2,%3,%4};"
                 :: "l"(p), "f"(v.x), "f"(v.y), "f"(v.z), "f"(v.w)
                 : "memory");
}

__device__ __forceinline__ void cp_async16(uint32_t sdst, const float4* gsrc, uint64_t pol) {
    asm volatile("cp.async.cg.shared.global.L2::cache_hint [%0], [%1], 16, %2;"
                 :: "r"(sdst), "l"(gsrc), "l"(pol) : "memory");
}

__device__ __forceinline__ void bulk_reduce_add_f32(float* gdst, uint32_t ssrc,
                                                    uint32_t bytes, uint64_t pol) {
    asm volatile(
        "cp.reduce.async.bulk.global.shared::cta.bulk_group.L2::cache_hint.add.f32 "
        "[%0], [%1], %2, %3;"
        :: "l"(gdst), "r"(ssrc), "r"(bytes), "l"(pol)
        : "memory");
}

__global__ void __launch_bounds__(THREADS_PER_BLOCK, 8)
scatter_kernel(const float4* __restrict__ deltas4,  // E * 80 float4
               const int*    __restrict__ i1,       // E
               const int*    __restrict__ i2,       // E
               float*        __restrict__ out,      // N * 128 fp32
               float4*       __restrict__ bout4,    // E * 16 float4
               long E, long nwarps)
{
    // Per-warp 3-stage ring: 3 x 1 KB = 3 KB/warp, 24 KB/block.
    __shared__ __align__(16) float4 buf[WARPS_PER_BLOCK][STAGES][64];

    const int wid  = threadIdx.x >> 5;
    const int lane = threadIdx.x & 31;
    const long gw  = (long)blockIdx.x * WARPS_PER_BLOCK + wid;

    const uint64_t pol_ef = make_evict_first_policy();
    const uint64_t pol_el = make_evict_last_policy();

    const uint32_t sbase = (uint32_t)__cvta_generic_to_shared(&buf[wid][0][0]);

    // Prologue: prefetch edge gw into stage 0.
    if (gw < E) {
        const float4* row0 = deltas4 + gw * 80;
        cp_async16(sbase + lane * 16,       row0 + lane,      pol_ef);
        cp_async16(sbase + 512 + lane * 16, row0 + 32 + lane, pol_ef);
    }
    asm volatile("cp.async.commit_group;" ::: "memory");

    int stage = 0;
    for (long e = gw; e < E; e += nwarps, stage = (stage == STAGES - 1) ? 0 : stage + 1) {
        const long en = e + nwarps;
        const int  sn = (stage == STAGES - 1) ? 0 : stage + 1;

        // Free the next stage for prefetch: with 3 stages, allowing 1 unread
        // bulk group means the group that read stage sn (2 iterations ago) is done.
        if (lane == 0)
            asm volatile("cp.async.bulk.wait_group.read 1;" ::: "memory");
        __syncwarp();

        // Prefetch NEXT edge's ux||uy into stage sn (zero register cost).
        if (en < E) {
            const float4* rown = deltas4 + en * 80;
            uint32_t sd = sbase + sn * STAGE_BYTES;
            cp_async16(sd + lane * 16,       rown + lane,      pol_ef);
            cp_async16(sd + 512 + lane * 16, rown + 32 + lane, pol_ef);
        }
        asm volatile("cp.async.commit_group;" ::: "memory");

        // b chunk for CURRENT edge: independent, straight to output.
        {
            const float4* row = deltas4 + e * 80;
            if (lane < 16) {
                float4 vb = ldg_stream(row + 64 + lane, pol_ef);
                stg_stream(bout4 + e * 16 + lane, vb);
            }
        }

        // Current stage's cp.async (committed LAST iteration / prologue) must
        // be complete: all groups but the newest.
        asm volatile("cp.async.wait_group 1;" ::: "memory");
        __syncwarp();

        if (lane == 0) {
            asm volatile("fence.proxy.async.shared::cta;" ::: "memory");
            int r1 = __ldg(&i1[e]);
            int r2 = __ldg(&i2[e]);
            uint32_t s = sbase + stage * STAGE_BYTES;
            bulk_reduce_add_f32(out + (long)r1 * 128, s,       512, pol_el);
            bulk_reduce_add_f32(out + (long)r2 * 128, s + 512, 512, pol_el);
            asm volatile("cp.async.bulk.commit_group;" ::: "memory");
        }
    }

    // Drain all pending bulk groups before exit.
    if (lane == 0)
        asm volatile("cp.async.bulk.wait_group 0;" ::: "memory");
}

extern "C" void kernel_launch(void* const* d_in, const int* in_sizes, int n_in,
                              void* d_out, int out_size)
{
    // metadata order: unary(N*128 f32), binary(E*64 f32), deltas(E*320 f32),
    //                 index1(E i32), index2(E i32)
    const long N = in_sizes[0] / 128;
    const long E = in_sizes[2] / 320;

    const float4* deltas4 = (const float4*)d_in[2];
    const int*    i1      = (const int*)d_in[3];
    const int*    i2      = (const int*)d_in[4];

    float*  out   = (float*)d_out;                       // N*128
    float4* bout4 = (float4*)((float*)d_out + N * 128);  // E*16 float4

    // 1) zero the scatter target and pin it in L2 (evict_last)
    {
        long n4 = (N * 128) / 4;
        int  threads = 256;
        long blocks = (n4 + threads - 1) / threads;
        zero_out_kernel<<<(unsigned)blocks, threads>>>((float4*)out, n4);
    }

    // 2) scatter-add (TMA bulk-reduce, cp.async-prefetched) + b copy
    {
        long nwarps = (long)GRID_BLOCKS * WARPS_PER_BLOCK;
        scatter_kernel<<<GRID_BLOCKS, THREADS_PER_BLOCK>>>(deltas4, i1, i2, out, bout4, E, nwarps);
    }
}